// round 14
// baseline (speedup 1.0000x reference)
#include <cuda_runtime.h>
#include <cuda_bf16.h>
#include <cstdint>

// ---------------- Problem constants ----------------
#define BATCH 64
#define NPATCH 196
#define D 768
#define T 8
#define HMETA 192
#define ROWS_TOT (BATCH * NPATCH)   // 12544
#define DD (D * D)
#define SPLITS 6
#define KC 64                        // K-chunk (bf16)
#define NKT 12                       // 768 / 64
#define ROWTILES1 98                 // 12544 / 128

// ---------------- Device scratch ----------------
__device__ __nv_bfloat16 g_patchesH[(size_t)(ROWS_TOT + 64) * D];
__device__ __nv_bfloat16 g_W1TH[DD];
__device__ __nv_bfloat16 g_dW1TH[(size_t)T * DD];
__device__ __nv_bfloat16 g_dW2TH[(size_t)T * DD];
__device__ __nv_bfloat16 g_mixW1TH[(size_t)BATCH * DD];             // 75 MB
__device__ __nv_bfloat16 g_pooled2H[BATCH * D];
__device__ float g_pooled[BATCH * D];
__device__ float g_pooled2[BATCH * D];
__device__ float g_base[BATCH * D];
__device__ float g_hid[BATCH * HMETA];
__device__ float g_coefs[BATCH * T];
__device__ float g_nb1[BATCH * D];
__device__ float g_nb2[BATCH * D];
__device__ float g_part[(size_t)SPLITS * BATCH * D];
__device__ float g_p1part[(size_t)ROWTILES1 * 2 * D];
__device__ float g_p2part[(size_t)BATCH * 2 * D];
__device__ float g_q[(size_t)T * BATCH * D];                        // delta GEMM results

// ---------------- PTX helpers (sm_80 baseline; ldmatrix sm_75+) ----------------
__device__ __forceinline__ void cpasync16(uint32_t dst, const void* src) {
    asm volatile("cp.async.cg.shared.global [%0], [%1], 16;" :: "r"(dst), "l"(src));
}
__device__ __forceinline__ void cpasync_commit() {
    asm volatile("cp.async.commit_group;" ::: "memory");
}
__device__ __forceinline__ void mma_bf16(float* c, const uint32_t* a, const uint32_t* b) {
    asm volatile("mma.sync.aligned.m16n8k16.row.col.f32.bf16.bf16.f32 "
        "{%0,%1,%2,%3}, {%4,%5,%6,%7}, {%8,%9}, {%0,%1,%2,%3};"
        : "+f"(c[0]), "+f"(c[1]), "+f"(c[2]), "+f"(c[3])
        : "r"(a[0]), "r"(a[1]), "r"(a[2]), "r"(a[3]), "r"(b[0]), "r"(b[1]));
}
__device__ __forceinline__ void ldm_x4(uint32_t& r0, uint32_t& r1, uint32_t& r2, uint32_t& r3,
                                       uint32_t addr) {
    asm volatile("ldmatrix.sync.aligned.m8n8.x4.shared.b16 {%0,%1,%2,%3}, [%4];"
        : "=r"(r0), "=r"(r1), "=r"(r2), "=r"(r3) : "r"(addr));
}
__device__ __forceinline__ uint32_t packbf2(float lo, float hi) {
    __nv_bfloat162 p = __floats2bfloat162_rn(lo, hi);
    return *reinterpret_cast<uint32_t*>(&p);
}

// ---------------- SMEM layout for mma_gemm_pool (exact R7) ----------------
#define HSTRIDE 72
#define ROWB (HSTRIDE * 2)                // 144 bytes per row
#define STAGEH (128 * HSTRIDE)            // 18432 bytes
#define SM_BYTES (4 * STAGEH * 2)         // 73728 bytes
#define SRED_OFF (128 * 132)

// load one 128x64 bf16 tile (row-major, ld = D halves) into smem [128][72]
__device__ __forceinline__ void load_tile64(__nv_bfloat16* dstBase,
                                            const __nv_bfloat16* src,
                                            int tid, int k0)
{
#pragma unroll
    for (int u = 0; u < 4; u++) {
        int q = tid + 256 * u;
        int row = q >> 3;
        int c8 = (q & 7) * 8;
        uint32_t dst = (uint32_t)__cvta_generic_to_shared(dstBase + row * HSTRIDE + c8);
        cpasync16(dst, src + (size_t)row * D + k0 + c8);
    }
}

// ---------------- bf16 mma GEMM + fused relu + mean-pool partials (exact R7) ----
__global__ __launch_bounds__(256, 2)
void mma_gemm_pool(const __nv_bfloat16* __restrict__ A, const __nv_bfloat16* __restrict__ B,
                   const float* __restrict__ bias, float* __restrict__ part,
                   long long sA, long long sB, int biasPerZ,
                   int Mvalid, int rowIsGlobal)
{
    extern __shared__ __nv_bfloat16 smh[];
    __nv_bfloat16* bufA[2] = { smh,              smh + 2 * STAGEH };
    __nv_bfloat16* bufB[2] = { smh + STAGEH,     smh + 3 * STAGEH };

    int tid = threadIdx.x;
    int wid = tid >> 5;
    int lane = tid & 31;
    int q = lane >> 2;
    int t = lane & 3;
    int warpRow = (wid & 3) * 32;
    int warpCol = (wid >> 2) * 64;

    int rowBase = blockIdx.y * 128;
    int colBase = blockIdx.x * 128;
    long long z = blockIdx.z;
    const __nv_bfloat16* Arow = A + z * sA + (size_t)rowBase * D;
    const __nv_bfloat16* Brow = B + z * sB + (size_t)colBase * D;
    const float* biasp = bias + (biasPerZ ? z * (long long)D : 0) + colBase;

    uint32_t smemU = (uint32_t)__cvta_generic_to_shared(smh);
    uint32_t bufAU[2] = { smemU,                 smemU + 2u * STAGEH * 2u };
    uint32_t bufBU[2] = { smemU + STAGEH * 2u,   smemU + 3u * STAGEH * 2u };
    uint32_t aOff = (uint32_t)((warpRow + (lane & 15)) * ROWB + ((lane >> 4) & 1) * 16);
    uint32_t bOff = (uint32_t)((warpCol + (lane & 7) + ((lane & 16) ? 8 : 0)) * ROWB
                               + ((lane & 8) ? 16 : 0));

    float acc[2][8][4];
#pragma unroll
    for (int mt = 0; mt < 2; mt++)
#pragma unroll
        for (int nt = 0; nt < 8; nt++)
#pragma unroll
            for (int e = 0; e < 4; e++) acc[mt][nt][e] = 0.f;

    load_tile64(bufA[0], Arow, tid, 0);
    load_tile64(bufB[0], Brow, tid, 0);
    cpasync_commit();
    load_tile64(bufA[1], Arow, tid, KC);
    load_tile64(bufB[1], Brow, tid, KC);
    cpasync_commit();

    for (int kt = 0; kt < NKT; kt++) {
        int buf = kt & 1;
        if (kt < NKT - 2) asm volatile("cp.async.wait_group 1;" ::: "memory");
        else              asm volatile("cp.async.wait_group 0;" ::: "memory");
        __syncthreads();

        uint32_t aBase = bufAU[buf] + aOff;
        uint32_t bBase = bufBU[buf] + bOff;
#pragma unroll
        for (int ks = 0; ks < 4; ks++) {
            uint32_t a[2][4];
#pragma unroll
            for (int mt = 0; mt < 2; mt++)
                ldm_x4(a[mt][0], a[mt][1], a[mt][2], a[mt][3],
                       aBase + mt * (16 * ROWB) + ks * 32);
            uint32_t b[8][2];
#pragma unroll
            for (int p = 0; p < 4; p++) {
                uint32_t r0, r1, r2, r3;
                ldm_x4(r0, r1, r2, r3, bBase + p * (16 * ROWB) + ks * 32);
                b[2 * p][0] = r0; b[2 * p][1] = r1;
                b[2 * p + 1][0] = r2; b[2 * p + 1][1] = r3;
            }
#pragma unroll
            for (int mt = 0; mt < 2; mt++)
#pragma unroll
                for (int nt = 0; nt < 8; nt++)
                    mma_bf16(acc[mt][nt], a[mt], b[nt]);
        }
        __syncthreads();

        if (kt + 2 < NKT) {
            int k0 = (kt + 2) * KC;
            load_tile64(bufA[buf], Arow, tid, k0);
            load_tile64(bufB[buf], Brow, tid, k0);
            cpasync_commit();
        }
    }

    // ---- epilogue: stage relu(D+bias)/196 into smem (masked rows) ----
    float* sD = reinterpret_cast<float*>(smh);   // 128 x 132 fp32
    const float invR = 1.0f / (float)NPATCH;
#pragma unroll
    for (int mt = 0; mt < 2; mt++) {
        int r0 = warpRow + mt * 16 + q;
        int r1 = r0 + 8;
        bool v0 = (rowBase + r0) < Mvalid;
        bool v1 = (rowBase + r1) < Mvalid;
#pragma unroll
        for (int nt = 0; nt < 8; nt++) {
            int c = warpCol + nt * 8 + t * 2;
            float bv0 = biasp[c], bv1 = biasp[c + 1];
            float x0 = fmaxf(acc[mt][nt][0] + bv0, 0.f) * invR;
            float x1 = fmaxf(acc[mt][nt][1] + bv1, 0.f) * invR;
            float x2 = fmaxf(acc[mt][nt][2] + bv0, 0.f) * invR;
            float x3 = fmaxf(acc[mt][nt][3] + bv1, 0.f) * invR;
            sD[(size_t)r0 * 132 + c]     = v0 ? x0 : 0.f;
            sD[(size_t)r0 * 132 + c + 1] = v0 ? x1 : 0.f;
            sD[(size_t)r1 * 132 + c]     = v1 ? x2 : 0.f;
            sD[(size_t)r1 * 132 + c + 1] = v1 ? x3 : 0.f;
        }
    }
    __syncthreads();

    // ---- two-phase deterministic column reduction ----
    float* sRed = reinterpret_cast<float*>(smh) + SRED_OFF;
    {
        int col = tid & 127;
        int half = tid >> 7;
        int rbound = 128;
        if (rowIsGlobal) {
            int b0 = rowBase / NPATCH;
            rbound = (b0 + 1) * NPATCH - rowBase;
            if (rbound > 128) rbound = 128;
        }
        float a0 = 0.f, a1 = 0.f;
        int rs = half * 64;
        for (int r = rs; r < rs + 64; r++) {
            float v = sD[(size_t)r * 132 + col];
            if (r < rbound) a0 += v; else a1 += v;
        }
        sRed[(half * 2 + 0) * 128 + col] = a0;
        sRed[(half * 2 + 1) * 128 + col] = a1;
    }
    __syncthreads();
    if (tid < 128) {
        float s0 = sRed[0 * 128 + tid] + sRed[2 * 128 + tid];
        float s1 = sRed[1 * 128 + tid] + sRed[3 * 128 + tid];
        int col = colBase + tid;
        if (rowIsGlobal) {
            part[((size_t)blockIdx.y * 2 + 0) * D + col] = s0;
            part[((size_t)blockIdx.y * 2 + 1) * D + col] = s1;
        } else {
            part[((size_t)z * gridDim.y + blockIdx.y) * D + col] = s0;
        }
    }
}

// ---------------- delta out GEMM: q[z] = pooled2H @ dW2TH[z]^T (bf16, M=64) ----
// Only the DELTA terms (multiplied by small coefs downstream) use bf16 here;
// the dominant W2 head stays on the fp32 path.
#define OSTAGEH (64 * HSTRIDE)            // 4608 halves
__global__ __launch_bounds__(128)
void mma_out_gemm(const __nv_bfloat16* __restrict__ A,
                  const __nv_bfloat16* __restrict__ Bd,
                  float* __restrict__ qout)
{
    __shared__ __nv_bfloat16 smh2[4 * OSTAGEH];   // 36864 B
    __nv_bfloat16* bufA[2] = { smh2,              smh2 + 2 * OSTAGEH };
    __nv_bfloat16* bufB[2] = { smh2 + OSTAGEH,    smh2 + 3 * OSTAGEH };

    int tid = threadIdx.x;
    int wid = tid >> 5;
    int lane = tid & 31;
    int q = lane >> 2;
    int t = lane & 3;

    int colBase = blockIdx.x * 64;
    int z = blockIdx.z;
    const __nv_bfloat16* Brow = Bd + (size_t)z * DD + (size_t)colBase * D;

    uint32_t smemU = (uint32_t)__cvta_generic_to_shared(smh2);
    uint32_t bufAU[2] = { smemU,                   smemU + 2u * OSTAGEH * 2u };
    uint32_t bufBU[2] = { smemU + OSTAGEH * 2u,    smemU + 3u * OSTAGEH * 2u };
    uint32_t aOff = (uint32_t)((wid * 16 + (lane & 15)) * ROWB + ((lane >> 4) & 1) * 16);
    uint32_t bOff = (uint32_t)(((lane & 7) + ((lane & 16) ? 8 : 0)) * ROWB
                               + ((lane & 8) ? 16 : 0));

    float acc[8][4];
#pragma unroll
    for (int nt = 0; nt < 8; nt++)
#pragma unroll
        for (int e = 0; e < 4; e++) acc[nt][e] = 0.f;

    auto load64 = [&](__nv_bfloat16* dst, const __nv_bfloat16* src, int k0) {
#pragma unroll
        for (int u = 0; u < 4; u++) {
            int qq = tid + 128 * u;
            int row = qq >> 3;
            int c8 = (qq & 7) * 8;
            uint32_t d = (uint32_t)__cvta_generic_to_shared(dst + row * HSTRIDE + c8);
            cpasync16(d, src + (size_t)row * D + k0 + c8);
        }
    };

    load64(bufA[0], A, 0);
    load64(bufB[0], Brow, 0);
    cpasync_commit();
    load64(bufA[1], A, KC);
    load64(bufB[1], Brow, KC);
    cpasync_commit();

    for (int kt = 0; kt < NKT; kt++) {
        int buf = kt & 1;
        if (kt < NKT - 2) asm volatile("cp.async.wait_group 1;" ::: "memory");
        else              asm volatile("cp.async.wait_group 0;" ::: "memory");
        __syncthreads();

        uint32_t aBase = bufAU[buf] + aOff;
        uint32_t bBase = bufBU[buf] + bOff;
#pragma unroll
        for (int ks = 0; ks < 4; ks++) {
            uint32_t a[4];
            ldm_x4(a[0], a[1], a[2], a[3], aBase + ks * 32);
            uint32_t b[8][2];
#pragma unroll
            for (int p = 0; p < 4; p++) {
                uint32_t r0, r1, r2, r3;
                ldm_x4(r0, r1, r2, r3, bBase + p * (16 * ROWB) + ks * 32);
                b[2 * p][0] = r0; b[2 * p][1] = r1;
                b[2 * p + 1][0] = r2; b[2 * p + 1][1] = r3;
            }
#pragma unroll
            for (int nt = 0; nt < 8; nt++)
                mma_bf16(acc[nt], a, b[nt]);
        }
        __syncthreads();

        if (kt + 2 < NKT) {
            int k0 = (kt + 2) * KC;
            load64(bufA[buf], A, k0);
            load64(bufB[buf], Brow, k0);
            cpasync_commit();
        }
    }

    float* dst = qout + (size_t)z * BATCH * D;
    int r0 = wid * 16 + q;
    int r1 = r0 + 8;
#pragma unroll
    for (int nt = 0; nt < 8; nt++) {
        int c = colBase + nt * 8 + t * 2;
        dst[(size_t)r0 * D + c]     = acc[nt][0];
        dst[(size_t)r0 * D + c + 1] = acc[nt][1];
        dst[(size_t)r1 * D + c]     = acc[nt][2];
        dst[(size_t)r1 * D + c + 1] = acc[nt][3];
    }
}

// ---------------- combine pool partials ----------------
__global__ void combine1_kernel(const float* __restrict__ part, float* __restrict__ pooled)
{
    int idx = blockIdx.x * blockDim.x + threadIdx.x;
    if (idx >= BATCH * D) return;
    int j = idx % D;
    int b = idx / D;
    int r0 = (b * NPATCH) / 128;
    int r1 = (b * NPATCH + NPATCH - 1) / 128;
    float s = 0.f;
    for (int ry = r0; ry <= r1; ry++) {
        int tb = (ry * 128) / NPATCH;
        int slot = (b == tb) ? 0 : 1;
        s += part[((size_t)ry * 2 + slot) * D + j];
    }
    pooled[idx] = s;
}

// combine2 -> fp32 pooled2 (fp32 head GEMM) + bf16 pooled2H (delta GEMMs)
__global__ void combine2_kernel(const float* __restrict__ part,
                                float* __restrict__ pooled2,
                                __nv_bfloat16* __restrict__ pooledH)
{
    int idx = blockIdx.x * blockDim.x + threadIdx.x;
    if (idx >= BATCH * D) return;
    int j = idx % D;
    int b = idx / D;
    float v = part[((size_t)b * 2 + 0) * D + j] + part[((size_t)b * 2 + 1) * D + j];
    pooled2[idx] = v;
    pooledH[idx] = __float2bfloat16_rn(v);
}

// ---------------- fused prep: patchify + transpose W1/dW1/dW2 -> bf16 ---------
#define PFBLK (ROWS_TOT * (D / 4) / 256)          // 9408
#define TRB_PER_Z ((D / 32) * (D / 32))           // 576
#define NZT (1 + 2 * T)                            // 17 matrices
#define TRBLK (NZT * TRB_PER_Z)                    // 9792

__global__ __launch_bounds__(256)
void prep_kernel(const float* __restrict__ x,
                 const float* __restrict__ W1, const float* __restrict__ dW1,
                 const float* __restrict__ dW2,
                 __nv_bfloat16* __restrict__ W1TH, __nv_bfloat16* __restrict__ dW1TH,
                 __nv_bfloat16* __restrict__ dW2TH,
                 uint2* __restrict__ outH)
{
    __shared__ float tile[32][33];
    int bid = blockIdx.x;
    int tid = threadIdx.x;

    if (bid < PFBLK) {
        int idx4 = bid * 256 + tid;
        int d4 = idx4 % (D / 4);
        int rem = idx4 / (D / 4);
        int n = rem % NPATCH;
        int b = rem / NPATCH;
        int d = d4 * 4;
        int c = d >> 8;
        int r2 = d & 255;
        int i = r2 >> 4;
        int j = r2 & 15;
        int hp = n / 14;
        int wp = n % 14;
        int src = ((b * 3 + c) * 224 + hp * 16 + i) * 224 + wp * 16 + j;
        float4 v = *reinterpret_cast<const float4*>(x + src);
        uint2 o;
        o.x = packbf2(v.x, v.y);
        o.y = packbf2(v.z, v.w);
        outH[idx4] = o;
    } else {
        int tb = bid - PFBLK;
        int zz = tb / TRB_PER_Z;          // 0..16
        int r  = tb - zz * TRB_PER_Z;
        int bx = r % (D / 32);
        int by = r / (D / 32);
        const float* src;
        __nv_bfloat16* dst;
        if (zz == 0)      { src = W1;                              dst = W1TH; }
        else if (zz <= T) { src = dW1 + (size_t)(zz - 1) * DD;     dst = dW1TH + (size_t)(zz - 1) * DD; }
        else              { src = dW2 + (size_t)(zz - T - 1) * DD; dst = dW2TH + (size_t)(zz - T - 1) * DD; }
        int tx = tid & 31;
        int ty = tid >> 5;
        int xx = bx * 32 + tx;
        int y0 = by * 32;
        for (int i = ty; i < 32; i += 8)
            tile[i][tx] = src[(size_t)(y0 + i) * D + xx];
        __syncthreads();
        int ox = by * 32 + tx;
        int oy0 = bx * 32;
        for (int i = ty; i < 32; i += 8)
            dst[(size_t)(oy0 + i) * D + ox] = __float2bfloat16_rn(tile[tx][i]);
    }
}

// ---------------- Small GEMM (M=64, fp32) with split-K partials ----------------
#define SBK 32
__global__ __launch_bounds__(256)
void small_gemm(const float* __restrict__ A, const float* __restrict__ B0,
                const float* __restrict__ Bd, long long sB,
                float* __restrict__ part, int N, int Kc)
{
    int z = blockIdx.z;
    const float* B;
    if (B0) B = (z == 0) ? B0 : (Bd + (long long)(z - 1) * sB);
    else    B = Bd + (long long)z * sB;

    int S = gridDim.y;
    int sy = blockIdx.y;
    int colBase = blockIdx.x * 64;
    int k0 = sy * Kc;

    __shared__ float As[SBK][64];
    __shared__ float Bs[SBK][64];

    int tid = threadIdx.x;
    int tx = tid & 15;
    int ty = tid >> 4;

    float acc[4][4];
#pragma unroll
    for (int i = 0; i < 4; i++)
#pragma unroll
        for (int j = 0; j < 4; j++) acc[i][j] = 0.f;

    for (int kb = 0; kb < Kc; kb += SBK) {
#pragma unroll
        for (int u = 0; u < 2; u++) {
            int qq = tid + 256 * u;
            int row = qq >> 3;
            int kq = (qq & 7) * 4;
            float4 av = *reinterpret_cast<const float4*>(A + (long long)row * D + k0 + kb + kq);
            As[kq + 0][row] = av.x;
            As[kq + 1][row] = av.y;
            As[kq + 2][row] = av.z;
            As[kq + 3][row] = av.w;
        }
#pragma unroll
        for (int u = 0; u < 2; u++) {
            int qq = tid + 256 * u;
            int k = qq >> 4;
            int col4 = (qq & 15) * 4;
            *reinterpret_cast<float4*>(&Bs[k][col4]) =
                *reinterpret_cast<const float4*>(B + (long long)(k0 + kb + k) * N + colBase + col4);
        }
        __syncthreads();
#pragma unroll
        for (int k = 0; k < SBK; k++) {
            float4 a4 = *reinterpret_cast<const float4*>(&As[k][ty * 4]);
            float4 b4 = *reinterpret_cast<const float4*>(&Bs[k][tx * 4]);
            float ra[4] = {a4.x, a4.y, a4.z, a4.w};
            float rb[4] = {b4.x, b4.y, b4.z, b4.w};
#pragma unroll
            for (int i = 0; i < 4; i++)
#pragma unroll
                for (int j = 0; j < 4; j++)
                    acc[i][j] = fmaf(ra[i], rb[j], acc[i][j]);
        }
        __syncthreads();
    }

    float* dst = part + ((long long)(z * S + sy) * 64) * N;
#pragma unroll
    for (int i = 0; i < 4; i++) {
        int r = ty * 4 + i;
        *reinterpret_cast<float4*>(dst + (long long)r * N + colBase + tx * 4) =
            make_float4(acc[i][0], acc[i][1], acc[i][2], acc[i][3]);
    }
}

__global__ void reduce_kernel(const float* __restrict__ part, float* __restrict__ dst,
                              const float* __restrict__ bias, int N, int relu)
{
    int idx = blockIdx.x * blockDim.x + threadIdx.x;
    if (idx >= BATCH * N) return;
    float v = bias ? bias[idx % N] : 0.f;
#pragma unroll
    for (int s = 0; s < SPLITS; s++) v += part[(long long)s * BATCH * N + idx];
    if (relu) v = fmaxf(v, 0.f);
    dst[idx] = v;
}

__global__ void coefs_kernel(const float* __restrict__ mw2, const float* __restrict__ mb2)
{
    int t = threadIdx.x;
    int b = t >> 3;
    int j = t & 7;
    float s = mb2[j];
    for (int k = 0; k < HMETA; k++)
        s = fmaf(g_hid[b * HMETA + k], mw2[k * T + j], s);
    g_coefs[b * T + j] = s;
}

// ---------------- fused mix: mixW1TH (blocks < MWBLK) + mixbias (rest) --------
#define MWBLK (DD / 4 / 256)             // 576
#define MBBLK ((BATCH * D + 255) / 256)  // 192

__global__ __launch_bounds__(256)
void mix_kernel(const float* __restrict__ b1, const float* __restrict__ db1,
                const float* __restrict__ b2, const float* __restrict__ db2)
{
    int bid = blockIdx.x;
    int tid = threadIdx.x;

    if (bid < MWBLK) {
        __shared__ float sc[BATCH * T];
        reinterpret_cast<float2*>(sc)[tid] = reinterpret_cast<const float2*>(g_coefs)[tid];
        __syncthreads();

        const long long per_b4 = DD / 4;
        long long r = (long long)bid * 256 + tid;

        const __nv_bfloat162* w2p = reinterpret_cast<const __nv_bfloat162*>(g_W1TH);
        float w[4];
        {
            float2 lo = __bfloat1622float2(w2p[2 * r]);
            float2 hi = __bfloat1622float2(w2p[2 * r + 1]);
            w[0] = lo.x; w[1] = lo.y; w[2] = hi.x; w[3] = hi.y;
        }
        float dv[T][4];
#pragma unroll
        for (int t = 0; t < T; t++) {
            const __nv_bfloat162* dp =
                reinterpret_cast<const __nv_bfloat162*>(g_dW1TH + (size_t)t * DD);
            float2 lo = __bfloat1622float2(dp[2 * r]);
            float2 hi = __bfloat1622float2(dp[2 * r + 1]);
            dv[t][0] = lo.x; dv[t][1] = lo.y; dv[t][2] = hi.x; dv[t][3] = hi.y;
        }

        uint2* outp = reinterpret_cast<uint2*>(g_mixW1TH) + r;
#pragma unroll 4
        for (int b = 0; b < BATCH; b++) {
            float v0 = w[0], v1 = w[1], v2 = w[2], v3 = w[3];
#pragma unroll
            for (int t = 0; t < T; t++) {
                float c = sc[b * T + t];
                v0 = fmaf(c, dv[t][0], v0);
                v1 = fmaf(c, dv[t][1], v1);
                v2 = fmaf(c, dv[t][2], v2);
                v3 = fmaf(c, dv[t][3], v3);
            }
            uint2 o;
            o.x = packbf2(v0, v1);
            o.y = packbf2(v2, v3);
            outp[(long long)b * per_b4] = o;
        }
    } else {
        int idx = (bid - MWBLK) * 256 + tid;
        if (idx >= BATCH * D) return;
        int j = idx % D;
        int b = idx / D;
        float c[T];
#pragma unroll
        for (int t = 0; t < T; t++) c[t] = g_coefs[b * T + t];
        float v1 = b1[j], v2 = b2[j];
#pragma unroll
        for (int t = 0; t < T; t++) {
            v1 = fmaf(c[t], db1[t * D + j], v1);
            v2 = fmaf(c[t], db2[t * D + j], v2);
        }
        g_nb1[idx] = v1;
        g_nb2[idx] = v2;
    }
}

// ---------------- final output: nb2 + Σ head-slabs + Σ_t c_t q[t] -------------
__global__ void final_out_kernel(const float* __restrict__ headpart,
                                 const float* __restrict__ qin,
                                 float* __restrict__ out)
{
    int idx = blockIdx.x * blockDim.x + threadIdx.x;
    if (idx >= BATCH * D) return;
    int b = idx / D;
    const int SLAB = BATCH * D;
    float v = g_nb2[idx];
#pragma unroll
    for (int s = 0; s < SPLITS; s++) v += headpart[(size_t)s * SLAB + idx];
#pragma unroll
    for (int t = 0; t < T; t++)
        v = fmaf(g_coefs[b * T + t], qin[(size_t)t * SLAB + idx], v);
    out[idx] = v;
}

// ---------------- launch ----------------
extern "C" void kernel_launch(void* const* d_in, const int* in_sizes, int n_in,
                              void* d_out, int out_size)
{
    const float* x   = (const float*)d_in[0];
    const float* W1  = (const float*)d_in[1];
    const float* b1  = (const float*)d_in[2];
    const float* W2  = (const float*)d_in[3];
    const float* b2  = (const float*)d_in[4];
    const float* dW1 = (const float*)d_in[5];
    const float* db1 = (const float*)d_in[6];
    const float* dW2 = (const float*)d_in[7];
    const float* db2 = (const float*)d_in[8];
    const float* mw1 = (const float*)d_in[9];
    const float* mb1 = (const float*)d_in[10];
    const float* mw2 = (const float*)d_in[11];
    const float* mb2 = (const float*)d_in[12];
    float* out = (float*)d_out;

    __nv_bfloat16 *patchesH, *W1TH, *dW1TH, *dW2TH, *mixW1TH, *pooled2H;
    float *pooled, *pooled2, *base, *hid, *part, *p1part, *p2part, *nb1, *qbuf;
    cudaGetSymbolAddress((void**)&patchesH, g_patchesH);
    cudaGetSymbolAddress((void**)&W1TH,     g_W1TH);
    cudaGetSymbolAddress((void**)&dW1TH,    g_dW1TH);
    cudaGetSymbolAddress((void**)&dW2TH,    g_dW2TH);
    cudaGetSymbolAddress((void**)&mixW1TH,  g_mixW1TH);
    cudaGetSymbolAddress((void**)&pooled2H, g_pooled2H);
    cudaGetSymbolAddress((void**)&pooled,   g_pooled);
    cudaGetSymbolAddress((void**)&pooled2,  g_pooled2);
    cudaGetSymbolAddress((void**)&base,     g_base);
    cudaGetSymbolAddress((void**)&hid,      g_hid);
    cudaGetSymbolAddress((void**)&part,     g_part);
    cudaGetSymbolAddress((void**)&p1part,   g_p1part);
    cudaGetSymbolAddress((void**)&p2part,   g_p2part);
    cudaGetSymbolAddress((void**)&nb1,      g_nb1);
    cudaGetSymbolAddress((void**)&qbuf,     g_q);

    cudaFuncSetAttribute(mma_gemm_pool, cudaFuncAttributeMaxDynamicSharedMemorySize, SM_BYTES);

    const int TPB = 256;

    // 1+2) fused patchify + 17 transposes (W1, dW1, dW2)
    prep_kernel<<<PFBLK + TRBLK, 256>>>(x, W1, dW1, dW2,
                                        W1TH, dW1TH, dW2TH, (uint2*)patchesH);

    // 3) GEMM1 (bf16 mma + ldmatrix) fused relu+pool partials
    mma_gemm_pool<<<dim3(D / 128, ROWTILES1, 1), 256, SM_BYTES>>>(
        patchesH, W1TH, b1, p1part, 0, 0, 0, ROWS_TOT, 1);
    combine1_kernel<<<(BATCH * D + TPB - 1) / TPB, TPB>>>(p1part, pooled);

    // 4) base = pooled @ W2 + b2   (fp32)
    small_gemm<<<dim3(D / 64, SPLITS, 1), 256>>>(pooled, W2, nullptr, 0, part, D, D / SPLITS);
    reduce_kernel<<<(BATCH * D + TPB - 1) / TPB, TPB>>>(part, base, b2, D, 0);

    // 5) hid = relu(base @ mw1 + mb1)  (fp32)
    small_gemm<<<dim3(HMETA / 64, SPLITS, 1), 256>>>(base, mw1, nullptr, 0, part, HMETA, D / SPLITS);
    reduce_kernel<<<(BATCH * HMETA + TPB - 1) / TPB, TPB>>>(part, hid, mb1, HMETA, 1);

    // 6) coefs
    coefs_kernel<<<1, 512>>>(mw2, mb2);

    // 7+8) fused mixW1TH + mixbias
    mix_kernel<<<MWBLK + MBBLK, 256>>>(b1, db1, b2, db2);

    // 9) GEMM2 (bf16 mma + ldmatrix, batched) fused relu+pool partials
    mma_gemm_pool<<<dim3(D / 128, 2, BATCH), 256, SM_BYTES>>>(
        patchesH, mixW1TH, nb1, p2part,
        (long long)NPATCH * D, (long long)DD, 1, NPATCH, 0);
    combine2_kernel<<<(BATCH * D + TPB - 1) / TPB, TPB>>>(p2part, pooled2, pooled2H);

    // 10) head: pooled2(fp32) @ W2(fp32) -> part slabs  (dominant term, full precision)
    small_gemm<<<dim3(D / 64, SPLITS, 1), 256>>>(pooled2, W2, nullptr, 0, part, D, D / SPLITS);

    // 11) deltas: q[t] = pooled2H @ dW2TH[t]  (bf16 tensor path; scaled by small coefs)
    mma_out_gemm<<<dim3(D / 64, 1, T), 128>>>(pooled2H, dW2TH, qbuf);

    // 12) final output
    final_out_kernel<<<(BATCH * D + TPB - 1) / TPB, TPB>>>(part, qbuf, out);
}

// round 15
// speedup vs baseline: 1.1455x; 1.1455x over previous
#include <cuda_runtime.h>
#include <cuda_bf16.h>
#include <cstdint>

// ---------------- Problem constants ----------------
#define BATCH 64
#define NPATCH 196
#define D 768
#define T 8
#define HMETA 192
#define ROWS_TOT (BATCH * NPATCH)   // 12544
#define DD (D * D)
#define SPLITS 12                    // split-K for small gemms (768/12 = 64)
#define KC 64                        // K-chunk (bf16)
#define NKT 12                       // 768 / 64
#define ROWTILES1 98                 // 12544 / 128

// ---------------- Device scratch ----------------
__device__ __nv_bfloat16 g_patchesH[(size_t)(ROWS_TOT + 64) * D];
__device__ __nv_bfloat16 g_W1TH[DD];
__device__ __nv_bfloat16 g_dW1TH[(size_t)T * DD];
__device__ __nv_bfloat16 g_mixW1TH[(size_t)BATCH * DD];             // 75 MB
__device__ float g_pooled[BATCH * D];
__device__ float g_pooled2[BATCH * D];
__device__ float g_base[BATCH * D];
__device__ float g_hid[BATCH * HMETA];
__device__ float g_coefs[BATCH * T];
__device__ float g_nb1[BATCH * D];
__device__ float g_nb2[BATCH * D];
__device__ float g_part[(size_t)(T + 1) * SPLITS * BATCH * D];      // 21 MB
__device__ float g_p1part[(size_t)ROWTILES1 * 2 * D];
__device__ float g_p2part[(size_t)BATCH * 2 * D];

// ---------------- PTX helpers (sm_80 baseline; ldmatrix sm_75+) ----------------
__device__ __forceinline__ void cpasync16(uint32_t dst, const void* src) {
    asm volatile("cp.async.cg.shared.global [%0], [%1], 16;" :: "r"(dst), "l"(src));
}
__device__ __forceinline__ void cpasync_commit() {
    asm volatile("cp.async.commit_group;" ::: "memory");
}
__device__ __forceinline__ void mma_bf16(float* c, const uint32_t* a, const uint32_t* b) {
    asm volatile("mma.sync.aligned.m16n8k16.row.col.f32.bf16.bf16.f32 "
        "{%0,%1,%2,%3}, {%4,%5,%6,%7}, {%8,%9}, {%0,%1,%2,%3};"
        : "+f"(c[0]), "+f"(c[1]), "+f"(c[2]), "+f"(c[3])
        : "r"(a[0]), "r"(a[1]), "r"(a[2]), "r"(a[3]), "r"(b[0]), "r"(b[1]));
}
__device__ __forceinline__ void ldm_x4(uint32_t& r0, uint32_t& r1, uint32_t& r2, uint32_t& r3,
                                       uint32_t addr) {
    asm volatile("ldmatrix.sync.aligned.m8n8.x4.shared.b16 {%0,%1,%2,%3}, [%4];"
        : "=r"(r0), "=r"(r1), "=r"(r2), "=r"(r3) : "r"(addr));
}
__device__ __forceinline__ uint32_t packbf2(float lo, float hi) {
    __nv_bfloat162 p = __floats2bfloat162_rn(lo, hi);
    return *reinterpret_cast<uint32_t*>(&p);
}

// ---------------- SMEM layout for mma_gemm_pool (exact R7) ----------------
#define HSTRIDE 72
#define ROWB (HSTRIDE * 2)                // 144 bytes per row
#define STAGEH (128 * HSTRIDE)            // 18432 bytes
#define SM_BYTES (4 * STAGEH * 2)         // 73728 bytes
#define SRED_OFF (128 * 132)

// load one 128x64 bf16 tile (row-major, ld = D halves) into smem [128][72]
__device__ __forceinline__ void load_tile64(__nv_bfloat16* dstBase,
                                            const __nv_bfloat16* src,
                                            int tid, int k0)
{
#pragma unroll
    for (int u = 0; u < 4; u++) {
        int q = tid + 256 * u;
        int row = q >> 3;
        int c8 = (q & 7) * 8;
        uint32_t dst = (uint32_t)__cvta_generic_to_shared(dstBase + row * HSTRIDE + c8);
        cpasync16(dst, src + (size_t)row * D + k0 + c8);
    }
}

// ---------------- bf16 mma GEMM + fused relu + mean-pool partials (exact R7) ----
__global__ __launch_bounds__(256, 2)
void mma_gemm_pool(const __nv_bfloat16* __restrict__ A, const __nv_bfloat16* __restrict__ B,
                   const float* __restrict__ bias, float* __restrict__ part,
                   long long sA, long long sB, int biasPerZ,
                   int Mvalid, int rowIsGlobal)
{
    extern __shared__ __nv_bfloat16 smh[];
    __nv_bfloat16* bufA[2] = { smh,              smh + 2 * STAGEH };
    __nv_bfloat16* bufB[2] = { smh + STAGEH,     smh + 3 * STAGEH };

    int tid = threadIdx.x;
    int wid = tid >> 5;
    int lane = tid & 31;
    int q = lane >> 2;
    int t = lane & 3;
    int warpRow = (wid & 3) * 32;
    int warpCol = (wid >> 2) * 64;

    int rowBase = blockIdx.y * 128;
    int colBase = blockIdx.x * 128;
    long long z = blockIdx.z;
    const __nv_bfloat16* Arow = A + z * sA + (size_t)rowBase * D;
    const __nv_bfloat16* Brow = B + z * sB + (size_t)colBase * D;
    const float* biasp = bias + (biasPerZ ? z * (long long)D : 0) + colBase;

    uint32_t smemU = (uint32_t)__cvta_generic_to_shared(smh);
    uint32_t bufAU[2] = { smemU,                 smemU + 2u * STAGEH * 2u };
    uint32_t bufBU[2] = { smemU + STAGEH * 2u,   smemU + 3u * STAGEH * 2u };
    uint32_t aOff = (uint32_t)((warpRow + (lane & 15)) * ROWB + ((lane >> 4) & 1) * 16);
    uint32_t bOff = (uint32_t)((warpCol + (lane & 7) + ((lane & 16) ? 8 : 0)) * ROWB
                               + ((lane & 8) ? 16 : 0));

    float acc[2][8][4];
#pragma unroll
    for (int mt = 0; mt < 2; mt++)
#pragma unroll
        for (int nt = 0; nt < 8; nt++)
#pragma unroll
            for (int e = 0; e < 4; e++) acc[mt][nt][e] = 0.f;

    load_tile64(bufA[0], Arow, tid, 0);
    load_tile64(bufB[0], Brow, tid, 0);
    cpasync_commit();
    load_tile64(bufA[1], Arow, tid, KC);
    load_tile64(bufB[1], Brow, tid, KC);
    cpasync_commit();

    for (int kt = 0; kt < NKT; kt++) {
        int buf = kt & 1;
        if (kt < NKT - 2) asm volatile("cp.async.wait_group 1;" ::: "memory");
        else              asm volatile("cp.async.wait_group 0;" ::: "memory");
        __syncthreads();

        uint32_t aBase = bufAU[buf] + aOff;
        uint32_t bBase = bufBU[buf] + bOff;
#pragma unroll
        for (int ks = 0; ks < 4; ks++) {
            uint32_t a[2][4];
#pragma unroll
            for (int mt = 0; mt < 2; mt++)
                ldm_x4(a[mt][0], a[mt][1], a[mt][2], a[mt][3],
                       aBase + mt * (16 * ROWB) + ks * 32);
            uint32_t b[8][2];
#pragma unroll
            for (int p = 0; p < 4; p++) {
                uint32_t r0, r1, r2, r3;
                ldm_x4(r0, r1, r2, r3, bBase + p * (16 * ROWB) + ks * 32);
                b[2 * p][0] = r0; b[2 * p][1] = r1;
                b[2 * p + 1][0] = r2; b[2 * p + 1][1] = r3;
            }
#pragma unroll
            for (int mt = 0; mt < 2; mt++)
#pragma unroll
                for (int nt = 0; nt < 8; nt++)
                    mma_bf16(acc[mt][nt], a[mt], b[nt]);
        }
        __syncthreads();

        if (kt + 2 < NKT) {
            int k0 = (kt + 2) * KC;
            load_tile64(bufA[buf], Arow, tid, k0);
            load_tile64(bufB[buf], Brow, tid, k0);
            cpasync_commit();
        }
    }

    // ---- epilogue: stage relu(D+bias)/196 into smem (masked rows) ----
    float* sD = reinterpret_cast<float*>(smh);   // 128 x 132 fp32
    const float invR = 1.0f / (float)NPATCH;
#pragma unroll
    for (int mt = 0; mt < 2; mt++) {
        int r0 = warpRow + mt * 16 + q;
        int r1 = r0 + 8;
        bool v0 = (rowBase + r0) < Mvalid;
        bool v1 = (rowBase + r1) < Mvalid;
#pragma unroll
        for (int nt = 0; nt < 8; nt++) {
            int c = warpCol + nt * 8 + t * 2;
            float bv0 = biasp[c], bv1 = biasp[c + 1];
            float x0 = fmaxf(acc[mt][nt][0] + bv0, 0.f) * invR;
            float x1 = fmaxf(acc[mt][nt][1] + bv1, 0.f) * invR;
            float x2 = fmaxf(acc[mt][nt][2] + bv0, 0.f) * invR;
            float x3 = fmaxf(acc[mt][nt][3] + bv1, 0.f) * invR;
            sD[(size_t)r0 * 132 + c]     = v0 ? x0 : 0.f;
            sD[(size_t)r0 * 132 + c + 1] = v0 ? x1 : 0.f;
            sD[(size_t)r1 * 132 + c]     = v1 ? x2 : 0.f;
            sD[(size_t)r1 * 132 + c + 1] = v1 ? x3 : 0.f;
        }
    }
    __syncthreads();

    // ---- two-phase deterministic column reduction ----
    float* sRed = reinterpret_cast<float*>(smh) + SRED_OFF;
    {
        int col = tid & 127;
        int half = tid >> 7;
        int rbound = 128;
        if (rowIsGlobal) {
            int b0 = rowBase / NPATCH;
            rbound = (b0 + 1) * NPATCH - rowBase;
            if (rbound > 128) rbound = 128;
        }
        float a0 = 0.f, a1 = 0.f;
        int rs = half * 64;
        for (int r = rs; r < rs + 64; r++) {
            float v = sD[(size_t)r * 132 + col];
            if (r < rbound) a0 += v; else a1 += v;
        }
        sRed[(half * 2 + 0) * 128 + col] = a0;
        sRed[(half * 2 + 1) * 128 + col] = a1;
    }
    __syncthreads();
    if (tid < 128) {
        float s0 = sRed[0 * 128 + tid] + sRed[2 * 128 + tid];
        float s1 = sRed[1 * 128 + tid] + sRed[3 * 128 + tid];
        int col = colBase + tid;
        if (rowIsGlobal) {
            part[((size_t)blockIdx.y * 2 + 0) * D + col] = s0;
            part[((size_t)blockIdx.y * 2 + 1) * D + col] = s1;
        } else {
            part[((size_t)z * gridDim.y + blockIdx.y) * D + col] = s0;
        }
    }
}

// ---------------- combine pool partials ----------------
__global__ void combine1_kernel(const float* __restrict__ part, float* __restrict__ pooled)
{
    int idx = blockIdx.x * blockDim.x + threadIdx.x;
    if (idx >= BATCH * D) return;
    int j = idx % D;
    int b = idx / D;
    int r0 = (b * NPATCH) / 128;
    int r1 = (b * NPATCH + NPATCH - 1) / 128;
    float s = 0.f;
    for (int ry = r0; ry <= r1; ry++) {
        int tb = (ry * 128) / NPATCH;
        int slot = (b == tb) ? 0 : 1;
        s += part[((size_t)ry * 2 + slot) * D + j];
    }
    pooled[idx] = s;
}

__global__ void combine2_kernel(const float* __restrict__ part, float* __restrict__ pooled)
{
    int idx = blockIdx.x * blockDim.x + threadIdx.x;
    if (idx >= BATCH * D) return;
    int j = idx % D;
    int b = idx / D;
    pooled[idx] = part[((size_t)b * 2 + 0) * D + j] + part[((size_t)b * 2 + 1) * D + j];
}

// ---------------- fused prep: patchify (bf16) + transpose W1/dW1 (bf16) -------
#define PFBLK (ROWS_TOT * (D / 4) / 256)          // 9408
#define TRB_PER_Z ((D / 32) * (D / 32))           // 576
#define TRBLK ((T + 1) * TRB_PER_Z)               // 5184

__global__ __launch_bounds__(256)
void prep_kernel(const float* __restrict__ x,
                 const float* __restrict__ W1, const float* __restrict__ dW1,
                 __nv_bfloat16* __restrict__ W1TH, __nv_bfloat16* __restrict__ dW1TH,
                 uint2* __restrict__ outH)
{
    __shared__ float tile[32][33];
    int bid = blockIdx.x;
    int tid = threadIdx.x;

    if (bid < PFBLK) {
        int idx4 = bid * 256 + tid;
        int d4 = idx4 % (D / 4);
        int rem = idx4 / (D / 4);
        int n = rem % NPATCH;
        int b = rem / NPATCH;
        int d = d4 * 4;
        int c = d >> 8;
        int r2 = d & 255;
        int i = r2 >> 4;
        int j = r2 & 15;
        int hp = n / 14;
        int wp = n % 14;
        int src = ((b * 3 + c) * 224 + hp * 16 + i) * 224 + wp * 16 + j;
        float4 v = *reinterpret_cast<const float4*>(x + src);
        uint2 o;
        o.x = packbf2(v.x, v.y);
        o.y = packbf2(v.z, v.w);
        outH[idx4] = o;
    } else {
        int tb = bid - PFBLK;
        int z  = tb / TRB_PER_Z;
        int r  = tb - z * TRB_PER_Z;
        int bx = r % (D / 32);
        int by = r / (D / 32);
        const float* src = (z == 0) ? W1 : dW1 + (size_t)(z - 1) * DD;
        __nv_bfloat16* dst = (z == 0) ? W1TH : dW1TH + (size_t)(z - 1) * DD;
        int tx = tid & 31;
        int ty = tid >> 5;
        int xx = bx * 32 + tx;
        int y0 = by * 32;
        for (int i = ty; i < 32; i += 8)
            tile[i][tx] = src[(size_t)(y0 + i) * D + xx];
        __syncthreads();
        int ox = by * 32 + tx;
        int oy0 = bx * 32;
        for (int i = ty; i < 32; i += 8)
            dst[(size_t)(oy0 + i) * D + ox] = __float2bfloat16_rn(tile[tx][i]);
    }
}

// ---------------- Small GEMM (M=64, fp32) with split-K partials ----------------
#define SBK 32
__global__ __launch_bounds__(256)
void small_gemm(const float* __restrict__ A, const float* __restrict__ B0,
                const float* __restrict__ Bd, long long sB,
                float* __restrict__ part, int N, int Kc)
{
    int z = blockIdx.z;
    const float* B;
    if (B0) B = (z == 0) ? B0 : (Bd + (long long)(z - 1) * sB);
    else    B = Bd + (long long)z * sB;

    int S = gridDim.y;
    int sy = blockIdx.y;
    int colBase = blockIdx.x * 64;
    int k0 = sy * Kc;

    __shared__ float As[SBK][64];
    __shared__ float Bs[SBK][64];

    int tid = threadIdx.x;
    int tx = tid & 15;
    int ty = tid >> 4;

    float acc[4][4];
#pragma unroll
    for (int i = 0; i < 4; i++)
#pragma unroll
        for (int j = 0; j < 4; j++) acc[i][j] = 0.f;

    for (int kb = 0; kb < Kc; kb += SBK) {
#pragma unroll
        for (int u = 0; u < 2; u++) {
            int qq = tid + 256 * u;
            int row = qq >> 3;
            int kq = (qq & 7) * 4;
            float4 av = *reinterpret_cast<const float4*>(A + (long long)row * D + k0 + kb + kq);
            As[kq + 0][row] = av.x;
            As[kq + 1][row] = av.y;
            As[kq + 2][row] = av.z;
            As[kq + 3][row] = av.w;
        }
#pragma unroll
        for (int u = 0; u < 2; u++) {
            int qq = tid + 256 * u;
            int k = qq >> 4;
            int col4 = (qq & 15) * 4;
            *reinterpret_cast<float4*>(&Bs[k][col4]) =
                *reinterpret_cast<const float4*>(B + (long long)(k0 + kb + k) * N + colBase + col4);
        }
        __syncthreads();
#pragma unroll
        for (int k = 0; k < SBK; k++) {
            float4 a4 = *reinterpret_cast<const float4*>(&As[k][ty * 4]);
            float4 b4 = *reinterpret_cast<const float4*>(&Bs[k][tx * 4]);
            float ra[4] = {a4.x, a4.y, a4.z, a4.w};
            float rb[4] = {b4.x, b4.y, b4.z, b4.w};
#pragma unroll
            for (int i = 0; i < 4; i++)
#pragma unroll
                for (int j = 0; j < 4; j++)
                    acc[i][j] = fmaf(ra[i], rb[j], acc[i][j]);
        }
        __syncthreads();
    }

    float* dst = part + ((long long)(z * S + sy) * 64) * N;
#pragma unroll
    for (int i = 0; i < 4; i++) {
        int r = ty * 4 + i;
        *reinterpret_cast<float4*>(dst + (long long)r * N + colBase + tx * 4) =
            make_float4(acc[i][0], acc[i][1], acc[i][2], acc[i][3]);
    }
}

__global__ void reduce_kernel(const float* __restrict__ part, float* __restrict__ dst,
                              const float* __restrict__ bias, int N, int relu)
{
    int idx = blockIdx.x * blockDim.x + threadIdx.x;
    if (idx >= BATCH * N) return;
    float v = bias ? bias[idx % N] : 0.f;
#pragma unroll
    for (int s = 0; s < SPLITS; s++) v += part[(long long)s * BATCH * N + idx];
    if (relu) v = fmaxf(v, 0.f);
    dst[idx] = v;
}

__global__ void coefs_kernel(const float* __restrict__ mw2, const float* __restrict__ mb2)
{
    int t = threadIdx.x;
    int b = t >> 3;
    int j = t & 7;
    float s = mb2[j];
    for (int k = 0; k < HMETA; k++)
        s = fmaf(g_hid[b * HMETA + k], mw2[k * T + j], s);
    g_coefs[b * T + j] = s;
}

// ---------------- fused mix: mixW1TH (blocks < MWBLK) + mixbias (rest) --------
#define MWBLK (DD / 4 / 256)             // 576
#define MBBLK ((BATCH * D + 255) / 256)  // 192

__global__ __launch_bounds__(256)
void mix_kernel(const float* __restrict__ b1, const float* __restrict__ db1,
                const float* __restrict__ b2, const float* __restrict__ db2)
{
    int bid = blockIdx.x;
    int tid = threadIdx.x;

    if (bid < MWBLK) {
        __shared__ float sc[BATCH * T];
        reinterpret_cast<float2*>(sc)[tid] = reinterpret_cast<const float2*>(g_coefs)[tid];
        __syncthreads();

        const long long per_b4 = DD / 4;
        long long r = (long long)bid * 256 + tid;

        const __nv_bfloat162* w2p = reinterpret_cast<const __nv_bfloat162*>(g_W1TH);
        float w[4];
        {
            float2 lo = __bfloat1622float2(w2p[2 * r]);
            float2 hi = __bfloat1622float2(w2p[2 * r + 1]);
            w[0] = lo.x; w[1] = lo.y; w[2] = hi.x; w[3] = hi.y;
        }
        float dv[T][4];
#pragma unroll
        for (int t = 0; t < T; t++) {
            const __nv_bfloat162* dp =
                reinterpret_cast<const __nv_bfloat162*>(g_dW1TH + (size_t)t * DD);
            float2 lo = __bfloat1622float2(dp[2 * r]);
            float2 hi = __bfloat1622float2(dp[2 * r + 1]);
            dv[t][0] = lo.x; dv[t][1] = lo.y; dv[t][2] = hi.x; dv[t][3] = hi.y;
        }

        uint2* outp = reinterpret_cast<uint2*>(g_mixW1TH) + r;
#pragma unroll 4
        for (int b = 0; b < BATCH; b++) {
            float v0 = w[0], v1 = w[1], v2 = w[2], v3 = w[3];
#pragma unroll
            for (int t = 0; t < T; t++) {
                float c = sc[b * T + t];
                v0 = fmaf(c, dv[t][0], v0);
                v1 = fmaf(c, dv[t][1], v1);
                v2 = fmaf(c, dv[t][2], v2);
                v3 = fmaf(c, dv[t][3], v3);
            }
            uint2 o;
            o.x = packbf2(v0, v1);
            o.y = packbf2(v2, v3);
            outp[(long long)b * per_b4] = o;
        }
    } else {
        int idx = (bid - MWBLK) * 256 + tid;
        if (idx >= BATCH * D) return;
        int j = idx % D;
        int b = idx / D;
        float c[T];
#pragma unroll
        for (int t = 0; t < T; t++) c[t] = g_coefs[b * T + t];
        float v1 = b1[j], v2 = b2[j];
#pragma unroll
        for (int t = 0; t < T; t++) {
            v1 = fmaf(c[t], db1[t * D + j], v1);
            v2 = fmaf(c[t], db2[t * D + j], v2);
        }
        g_nb1[idx] = v1;
        g_nb2[idx] = v2;
    }
}

__global__ void final_out_kernel(const float* __restrict__ part, float* __restrict__ out)
{
    int idx = blockIdx.x * blockDim.x + threadIdx.x;
    if (idx >= BATCH * D) return;
    int b = idx / D;
    const int SLAB = BATCH * D;
    float v = g_nb2[idx];
#pragma unroll
    for (int s = 0; s < SPLITS; s++) v += part[(long long)s * SLAB + idx];
#pragma unroll
    for (int t = 0; t < T; t++) {
        float qv = 0.f;
#pragma unroll
        for (int s = 0; s < SPLITS; s++)
            qv += part[(long long)((t + 1) * SPLITS + s) * SLAB + idx];
        v = fmaf(g_coefs[b * T + t], qv, v);
    }
    out[idx] = v;
}

// ---------------- launch ----------------
extern "C" void kernel_launch(void* const* d_in, const int* in_sizes, int n_in,
                              void* d_out, int out_size)
{
    const float* x   = (const float*)d_in[0];
    const float* W1  = (const float*)d_in[1];
    const float* b1  = (const float*)d_in[2];
    const float* W2  = (const float*)d_in[3];
    const float* b2  = (const float*)d_in[4];
    const float* dW1 = (const float*)d_in[5];
    const float* db1 = (const float*)d_in[6];
    const float* dW2 = (const float*)d_in[7];
    const float* db2 = (const float*)d_in[8];
    const float* mw1 = (const float*)d_in[9];
    const float* mb1 = (const float*)d_in[10];
    const float* mw2 = (const float*)d_in[11];
    const float* mb2 = (const float*)d_in[12];
    float* out = (float*)d_out;

    __nv_bfloat16 *patchesH, *W1TH, *dW1TH, *mixW1TH;
    float *pooled, *pooled2, *base, *hid, *part, *p1part, *p2part, *nb1;
    cudaGetSymbolAddress((void**)&patchesH, g_patchesH);
    cudaGetSymbolAddress((void**)&W1TH,     g_W1TH);
    cudaGetSymbolAddress((void**)&dW1TH,    g_dW1TH);
    cudaGetSymbolAddress((void**)&mixW1TH,  g_mixW1TH);
    cudaGetSymbolAddress((void**)&pooled,   g_pooled);
    cudaGetSymbolAddress((void**)&pooled2,  g_pooled2);
    cudaGetSymbolAddress((void**)&base,     g_base);
    cudaGetSymbolAddress((void**)&hid,      g_hid);
    cudaGetSymbolAddress((void**)&part,     g_part);
    cudaGetSymbolAddress((void**)&p1part,   g_p1part);
    cudaGetSymbolAddress((void**)&p2part,   g_p2part);
    cudaGetSymbolAddress((void**)&nb1,      g_nb1);

    cudaFuncSetAttribute(mma_gemm_pool, cudaFuncAttributeMaxDynamicSharedMemorySize, SM_BYTES);

    const int TPB = 256;

    // 1+2) fused patchify + transpose
    prep_kernel<<<PFBLK + TRBLK, 256>>>(x, W1, dW1, W1TH, dW1TH, (uint2*)patchesH);

    // 3) GEMM1 (bf16 mma + ldmatrix) fused relu+pool partials
    mma_gemm_pool<<<dim3(D / 128, ROWTILES1, 1), 256, SM_BYTES>>>(
        patchesH, W1TH, b1, p1part, 0, 0, 0, ROWS_TOT, 1);
    combine1_kernel<<<(BATCH * D + TPB - 1) / TPB, TPB>>>(p1part, pooled);

    // 4) base = pooled @ W2 + b2  (split-K x12)
    small_gemm<<<dim3(D / 64, SPLITS, 1), 256>>>(pooled, W2, nullptr, 0, part, D, D / SPLITS);
    reduce_kernel<<<(BATCH * D + TPB - 1) / TPB, TPB>>>(part, base, b2, D, 0);

    // 5) hid = relu(base @ mw1 + mb1)  (split-K x12)
    small_gemm<<<dim3(HMETA / 64, SPLITS, 1), 256>>>(base, mw1, nullptr, 0, part, HMETA, D / SPLITS);
    reduce_kernel<<<(BATCH * HMETA + TPB - 1) / TPB, TPB>>>(part, hid, mb1, HMETA, 1);

    // 6) coefs
    coefs_kernel<<<1, 512>>>(mw2, mb2);

    // 7+8) fused mixW1TH + mixbias
    mix_kernel<<<MWBLK + MBBLK, 256>>>(b1, db1, b2, db2);

    // 9) GEMM2 (bf16 mma + ldmatrix, batched) fused relu+pool partials
    mma_gemm_pool<<<dim3(D / 128, 2, BATCH), 256, SM_BYTES>>>(
        patchesH, mixW1TH, nb1, p2part,
        (long long)NPATCH * D, (long long)DD, 1, NPATCH, 0);
    combine2_kernel<<<(BATCH * D + TPB - 1) / TPB, TPB>>>(p2part, pooled2);

    // 10+11) q (dW2 tasks) + W2 head via z=0 (split-K x12 partials)
    small_gemm<<<dim3(D / 64, SPLITS, T + 1), 256>>>(pooled2, W2, dW2, (long long)DD, part, D, D / SPLITS);

    // 12) final output
    final_out_kernel<<<(BATCH * D + TPB - 1) / TPB, TPB>>>(part, out);
}